// round 1
// baseline (speedup 1.0000x reference)
#include <cuda_runtime.h>
#include <cuda_bf16.h>
#include <cstdint>

// Problem constants (fixed shapes for this problem instance)
constexpr int MDIM = 4096;      // B*S = 2*2048
constexpr int KDIM = 4096;
constexpr int NDIM = 11008;
constexpr int K3   = 3 * KDIM;  // 12288 : stacked-K for bf16x3 split GEMM
constexpr int GRP  = 128;       // quant group size

// ---------------------------------------------------------------------------
// Device scratch (allocation-free rule: __device__ globals)
//   g_A : [MDIM][3K]  = [x_hi | x_hi | x_lo]   (bf16)
//   g_B : [NDIM][3K]  = [w_hi | w_lo | w_hi]   (bf16, k-contiguous per n row)
// sum over K' = x_hi*w_hi + x_hi*w_lo + x_lo*w_hi  (drop x_lo*w_lo ~ 2^-32)
// ---------------------------------------------------------------------------
__device__ __nv_bfloat16 g_A[(size_t)MDIM * K3];
__device__ __nv_bfloat16 g_B[(size_t)NDIM * K3];

// ---------------------------------------------------------------------------
// PTX helpers
// ---------------------------------------------------------------------------
__device__ __forceinline__ uint32_t smem_u32(const void* p) {
    return (uint32_t)__cvta_generic_to_shared(p);
}
__device__ __forceinline__ void cp_async16(void* smem, const void* gmem) {
    asm volatile("cp.async.cg.shared.global [%0], [%1], 16;\n"
                 :: "r"(smem_u32(smem)), "l"(gmem));
}
__device__ __forceinline__ void cp_commit() {
    asm volatile("cp.async.commit_group;\n");
}
__device__ __forceinline__ void cp_wait1() {
    asm volatile("cp.async.wait_group 1;\n");
}
__device__ __forceinline__ void cp_wait0() {
    asm volatile("cp.async.wait_group 0;\n");
}
__device__ __forceinline__ void ldmatrix_x4(uint32_t& r0, uint32_t& r1,
                                            uint32_t& r2, uint32_t& r3,
                                            uint32_t addr) {
    asm volatile("ldmatrix.sync.aligned.m8n8.x4.shared.b16 {%0,%1,%2,%3}, [%4];\n"
                 : "=r"(r0), "=r"(r1), "=r"(r2), "=r"(r3) : "r"(addr));
}
__device__ __forceinline__ void ldmatrix_x2(uint32_t& r0, uint32_t& r1, uint32_t addr) {
    asm volatile("ldmatrix.sync.aligned.m8n8.x2.shared.b16 {%0,%1}, [%2];\n"
                 : "=r"(r0), "=r"(r1) : "r"(addr));
}
__device__ __forceinline__ void mma_bf16(float& c0, float& c1, float& c2, float& c3,
                                         uint32_t a0, uint32_t a1, uint32_t a2, uint32_t a3,
                                         uint32_t b0, uint32_t b1) {
    asm volatile("mma.sync.aligned.m16n8k16.row.col.f32.bf16.bf16.f32 "
                 "{%0,%1,%2,%3}, {%4,%5,%6,%7}, {%8,%9}, {%0,%1,%2,%3};\n"
                 : "+f"(c0), "+f"(c1), "+f"(c2), "+f"(c3)
                 : "r"(a0), "r"(a1), "r"(a2), "r"(a3), "r"(b0), "r"(b1));
}

// ---------------------------------------------------------------------------
// Kernel 1: split x (fp32) -> A = [x_hi | x_hi | x_lo] bf16, [MDIM][3K]
// ---------------------------------------------------------------------------
__global__ void split_x_kernel(const float* __restrict__ x) {
    int64_t idx = (int64_t)blockIdx.x * blockDim.x + threadIdx.x;
    constexpr int64_t total = (int64_t)MDIM * KDIM / 4;
    if (idx >= total) return;
    int64_t m  = idx / (KDIM / 4);
    int64_t kq = idx % (KDIM / 4);
    int64_t k  = kq * 4;

    float4 v = reinterpret_cast<const float4*>(x)[idx];
    float f[4] = {v.x, v.y, v.z, v.w};
    __nv_bfloat16 hi[4], lo[4];
#pragma unroll
    for (int i = 0; i < 4; i++) {
        hi[i] = __float2bfloat16(f[i]);
        lo[i] = __float2bfloat16(f[i] - __bfloat162float(hi[i]));
    }
    uint2 phi, plo;
    {
        __nv_bfloat162 h0 = __nv_bfloat162(hi[0], hi[1]);
        __nv_bfloat162 h1 = __nv_bfloat162(hi[2], hi[3]);
        __nv_bfloat162 l0 = __nv_bfloat162(lo[0], lo[1]);
        __nv_bfloat162 l1 = __nv_bfloat162(lo[2], lo[3]);
        phi.x = *reinterpret_cast<uint32_t*>(&h0);
        phi.y = *reinterpret_cast<uint32_t*>(&h1);
        plo.x = *reinterpret_cast<uint32_t*>(&l0);
        plo.y = *reinterpret_cast<uint32_t*>(&l1);
    }
    size_t base = (size_t)m * K3 + k;
    *reinterpret_cast<uint2*>(&g_A[base])            = phi;  // seg0: x_hi
    *reinterpret_cast<uint2*>(&g_A[base + KDIM])     = phi;  // seg1: x_hi
    *reinterpret_cast<uint2*>(&g_A[base + 2 * KDIM]) = plo;  // seg2: x_lo
}

// ---------------------------------------------------------------------------
// Kernel 2: dequant + split + transpose weights
//   qweight [K, N/8] int32 -> B[n][k] with segments [w_hi | w_lo | w_hi]
// Tile: 64 k x 64 n per block, transpose through smem, 16B global writes.
// ---------------------------------------------------------------------------
__global__ void dequant_w_kernel(const int* __restrict__ qw,
                                 const int* __restrict__ qz,
                                 const float* __restrict__ sc) {
    __shared__ __nv_bfloat16 sh_hi[64][72];  // [n_local][k_local], row = 144B (16B-aligned)
    __shared__ __nv_bfloat16 sh_lo[64][72];
    __shared__ float s_scale[64];
    __shared__ int   s_z[8];

    const int tid = threadIdx.x;
    const int n0 = blockIdx.x * 64;
    const int k0 = blockIdx.y * 64;
    const int group = k0 / GRP;          // 64 | 128, so tile sits in one group
    const int pw = NDIM / 8;             // packed width

    if (tid < 64) s_scale[tid] = sc[(size_t)group * NDIM + n0 + tid];
    if (tid < 8)  s_z[tid]     = qz[(size_t)group * pw + n0 / 8 + tid];
    __syncthreads();

    const int shifts[8] = {0, 16, 4, 20, 8, 24, 12, 28};

    for (int i = tid; i < 64 * 8; i += 256) {
        int kl = i >> 3;
        int p  = i & 7;
        int packed = qw[(size_t)(k0 + kl) * pw + n0 / 8 + p];
        int zp = s_z[p];
#pragma unroll
        for (int j = 0; j < 8; j++) {
            int v = (packed >> shifts[j]) & 0xF;
            int z = (zp     >> shifts[j]) & 0xF;
            int nl = p * 8 + j;
            float w = (float)(v - z) * s_scale[nl];
            __nv_bfloat16 hi = __float2bfloat16(w);
            float rem = w - __bfloat162float(hi);
            sh_hi[nl][kl] = hi;
            sh_lo[nl][kl] = __float2bfloat16(rem);
        }
    }
    __syncthreads();

    // write: 64 n rows x 8 chunks of 8 bf16 (16B each)
    for (int i = tid; i < 64 * 8; i += 256) {
        int nl = i >> 3;
        int ck = (i & 7) * 8;
        uint4 hi = *reinterpret_cast<const uint4*>(&sh_hi[nl][ck]);
        uint4 lo = *reinterpret_cast<const uint4*>(&sh_lo[nl][ck]);
        size_t row = (size_t)(n0 + nl) * K3;
        *reinterpret_cast<uint4*>(&g_B[row + k0 + ck])            = hi;  // seg0: w_hi
        *reinterpret_cast<uint4*>(&g_B[row + KDIM + k0 + ck])     = lo;  // seg1: w_lo
        *reinterpret_cast<uint4*>(&g_B[row + 2 * KDIM + k0 + ck]) = hi;  // seg2: w_hi
    }
}

// ---------------------------------------------------------------------------
// Kernel 3: bf16 GEMM  out[M,N] = A[M,K3] * B[N,K3]^T + bias
// BM=128 BN=128 BK=32, 256 threads (8 warps, 2x4), warp tile 64x32,
// cp.async double-buffered, ldmatrix + mma.m16n8k16, fp32 accumulate.
// ---------------------------------------------------------------------------
constexpr int BM = 128, BN = 128, BK = 32;
constexpr int LDS_PAD = 8;
constexpr int LDA = BK + LDS_PAD;  // 40 elems = 80B row: conflict-free ldmatrix

__global__ __launch_bounds__(256, 2)
void gemm_bf16_kernel(const float* __restrict__ bias, float* __restrict__ out) {
    __shared__ __nv_bfloat16 As[2][BM][LDA];
    __shared__ __nv_bfloat16 Bs[2][BN][LDA];

    const int tid  = threadIdx.x;
    const int lane = tid & 31;
    const int warp = tid >> 5;
    const int m0 = blockIdx.y * BM;
    const int n0 = blockIdx.x * BN;
    const int wm = (warp >> 2) * 64;  // warp m-offset (0/64)
    const int wn = (warp & 3) * 32;   // warp n-offset (0/32/64/96)

    float acc[4][4][4];
#pragma unroll
    for (int a = 0; a < 4; a++)
#pragma unroll
        for (int b = 0; b < 4; b++)
#pragma unroll
            for (int c = 0; c < 4; c++) acc[a][b][c] = 0.0f;

    const __nv_bfloat16* Ag = g_A;
    const __nv_bfloat16* Bg = g_B;

    constexpr int T = K3 / BK;  // 384

    // --- stage 0 prefetch ---
    {
#pragma unroll
        for (int i = 0; i < 2; i++) {
            int c = tid + i * 256;          // 0..511
            int row = c >> 2;
            int kk  = (c & 3) * 8;
            cp_async16(&As[0][row][kk], Ag + (size_t)(m0 + row) * K3 + kk);
            cp_async16(&Bs[0][row][kk], Bg + (size_t)(n0 + row) * K3 + kk);
        }
        cp_commit();
    }

    for (int t = 0; t < T; t++) {
        if (t + 1 < T) {
            int s = (t + 1) & 1;
            int bk = (t + 1) * BK;
#pragma unroll
            for (int i = 0; i < 2; i++) {
                int c = tid + i * 256;
                int row = c >> 2;
                int kk  = (c & 3) * 8;
                cp_async16(&As[s][row][kk], Ag + (size_t)(m0 + row) * K3 + bk + kk);
                cp_async16(&Bs[s][row][kk], Bg + (size_t)(n0 + row) * K3 + bk + kk);
            }
            cp_commit();
            cp_wait1();
        } else {
            cp_wait0();
        }
        __syncthreads();

        const int s = t & 1;
#pragma unroll
        for (int ks = 0; ks < 2; ks++) {
            uint32_t afr[4][4];
            uint32_t bfr[4][2];
#pragma unroll
            for (int mt = 0; mt < 4; mt++) {
                uint32_t addr = smem_u32(
                    &As[s][wm + mt * 16 + (lane & 15)][ks * 16 + (lane >> 4) * 8]);
                ldmatrix_x4(afr[mt][0], afr[mt][1], afr[mt][2], afr[mt][3], addr);
            }
#pragma unroll
            for (int nt = 0; nt < 4; nt++) {
                uint32_t addr = smem_u32(
                    &Bs[s][wn + nt * 8 + (lane & 7)][ks * 16 + ((lane >> 3) & 1) * 8]);
                ldmatrix_x2(bfr[nt][0], bfr[nt][1], addr);
            }
#pragma unroll
            for (int mt = 0; mt < 4; mt++)
#pragma unroll
                for (int nt = 0; nt < 4; nt++)
                    mma_bf16(acc[mt][nt][0], acc[mt][nt][1], acc[mt][nt][2], acc[mt][nt][3],
                             afr[mt][0], afr[mt][1], afr[mt][2], afr[mt][3],
                             bfr[nt][0], bfr[nt][1]);
        }
        __syncthreads();
    }

    // --- epilogue: += bias, write fp32 ---
#pragma unroll
    for (int mt = 0; mt < 4; mt++) {
#pragma unroll
        for (int nt = 0; nt < 4; nt++) {
            int r = m0 + wm + mt * 16 + (lane >> 2);
            int c = n0 + wn + nt * 8 + (lane & 3) * 2;
            float2 bv = *reinterpret_cast<const float2*>(&bias[c]);
            float2 v0 = {acc[mt][nt][0] + bv.x, acc[mt][nt][1] + bv.y};
            float2 v1 = {acc[mt][nt][2] + bv.x, acc[mt][nt][3] + bv.y};
            *reinterpret_cast<float2*>(&out[(size_t)r * NDIM + c])       = v0;
            *reinterpret_cast<float2*>(&out[(size_t)(r + 8) * NDIM + c]) = v1;
        }
    }
}

// ---------------------------------------------------------------------------
// Launch
// ---------------------------------------------------------------------------
extern "C" void kernel_launch(void* const* d_in, const int* in_sizes, int n_in,
                              void* d_out, int out_size) {
    const float* x    = (const float*)d_in[0];
    const int*   qw   = (const int*)d_in[1];
    const int*   qz   = (const int*)d_in[2];
    const float* sc   = (const float*)d_in[3];
    const float* bias = (const float*)d_in[4];
    float* out = (float*)d_out;

    // 1) split x -> g_A
    {
        int64_t total = (int64_t)MDIM * KDIM / 4;
        int blocks = (int)((total + 255) / 256);
        split_x_kernel<<<blocks, 256>>>(x);
    }
    // 2) dequant + split weights -> g_B
    {
        dim3 grid(NDIM / 64, KDIM / 64);
        dequant_w_kernel<<<grid, 256>>>(qw, qz, sc);
    }
    // 3) GEMM
    {
        dim3 grid(NDIM / BN, MDIM / BM);
        gemm_bf16_kernel<<<grid, 256>>>(bias, out);
    }
}

// round 3
// speedup vs baseline: 2.7365x; 2.7365x over previous
#include <cuda_runtime.h>
#include <cuda_fp16.h>
#include <cstdint>

// Shapes (fixed for this problem)
constexpr int MDIM = 4096;   // B*S
constexpr int KDIM = 4096;
constexpr int NDIM = 11008;
constexpr int GRP  = 128;

// -----------------------------------------------------------------------
// Scratch (allocation-free rule: __device__ globals)
//   g_A: [M][K] fp16 = fp16(x)
//   g_B: [N][K] fp16 = fp16((v - z) * scale)   (k-contiguous rows)
// Error model: out rel_err ~ sqrt(2) * 2^-11/sqrt(3) ~ 4e-4 < 1e-3.
// -----------------------------------------------------------------------
__device__ __half g_A[(size_t)MDIM * KDIM];
__device__ __half g_B[(size_t)NDIM * KDIM];

// ========================= PTX helpers =========================
__device__ __forceinline__ uint32_t smem_u32(const void* p) {
    return (uint32_t)__cvta_generic_to_shared(p);
}
__device__ __forceinline__ void cp_async16(uint32_t smem, const void* gmem) {
    asm volatile("cp.async.cg.shared.global [%0], [%1], 16;\n"
                 :: "r"(smem), "l"(gmem));
}
__device__ __forceinline__ void cp_commit() {
    asm volatile("cp.async.commit_group;\n");
}
__device__ __forceinline__ void cp_wait2() {
    asm volatile("cp.async.wait_group 2;\n");
}
__device__ __forceinline__ void ldmatrix_x4(uint32_t& r0, uint32_t& r1,
                                            uint32_t& r2, uint32_t& r3,
                                            uint32_t addr) {
    asm volatile("ldmatrix.sync.aligned.m8n8.x4.shared.b16 {%0,%1,%2,%3}, [%4];\n"
                 : "=r"(r0), "=r"(r1), "=r"(r2), "=r"(r3) : "r"(addr));
}
__device__ __forceinline__ void ldmatrix_x2(uint32_t& r0, uint32_t& r1, uint32_t addr) {
    asm volatile("ldmatrix.sync.aligned.m8n8.x2.shared.b16 {%0,%1}, [%2];\n"
                 : "=r"(r0), "=r"(r1) : "r"(addr));
}
__device__ __forceinline__ void mma_f16(float& c0, float& c1, float& c2, float& c3,
                                        uint32_t a0, uint32_t a1, uint32_t a2, uint32_t a3,
                                        uint32_t b0, uint32_t b1) {
    asm volatile("mma.sync.aligned.m16n8k16.row.col.f32.f16.f16.f32 "
                 "{%0,%1,%2,%3}, {%4,%5,%6,%7}, {%8,%9}, {%0,%1,%2,%3};\n"
                 : "+f"(c0), "+f"(c1), "+f"(c2), "+f"(c3)
                 : "r"(a0), "r"(a1), "r"(a2), "r"(a3), "r"(b0), "r"(b1));
}

// ========================= Kernel 1: x -> fp16 =========================
__global__ void conv_x_kernel(const float* __restrict__ x) {
    size_t i = (size_t)blockIdx.x * blockDim.x + threadIdx.x;  // per 8 floats
    const float4* x4 = reinterpret_cast<const float4*>(x);
    float4 a = x4[2 * i];
    float4 b = x4[2 * i + 1];
    __half2 h0 = __floats2half2_rn(a.x, a.y);
    __half2 h1 = __floats2half2_rn(a.z, a.w);
    __half2 h2 = __floats2half2_rn(b.x, b.y);
    __half2 h3 = __floats2half2_rn(b.z, b.w);
    uint4 o;
    o.x = *reinterpret_cast<uint32_t*>(&h0);
    o.y = *reinterpret_cast<uint32_t*>(&h1);
    o.z = *reinterpret_cast<uint32_t*>(&h2);
    o.w = *reinterpret_cast<uint32_t*>(&h3);
    reinterpret_cast<uint4*>(g_A)[i] = o;
}

// ========================= Kernel 2: dequant W -> fp16 [N][K] ===========
__global__ void dequant_w_kernel(const int* __restrict__ qw,
                                 const int* __restrict__ qz,
                                 const float* __restrict__ sc) {
    __shared__ __half sh[64][72];   // [n_local][k_local], row=144B (16B aligned)
    __shared__ float  s_scale[64];
    __shared__ int    s_z[8];

    const int tid = threadIdx.x;
    const int n0 = blockIdx.x * 64;
    const int k0 = blockIdx.y * 64;
    const int group = k0 / GRP;
    const int pw = NDIM / 8;

    if (tid < 64) s_scale[tid] = sc[(size_t)group * NDIM + n0 + tid];
    if (tid < 8)  s_z[tid]     = qz[(size_t)group * pw + n0 / 8 + tid];
    __syncthreads();

    const int shifts[8] = {0, 16, 4, 20, 8, 24, 12, 28};
    for (int i = tid; i < 64 * 8; i += 256) {
        int kl = i >> 3;
        int p  = i & 7;
        int packed = qw[(size_t)(k0 + kl) * pw + n0 / 8 + p];
        int zp = s_z[p];
#pragma unroll
        for (int j = 0; j < 8; j++) {
            int v = (packed >> shifts[j]) & 0xF;
            int z = (zp     >> shifts[j]) & 0xF;
            int nl = p * 8 + j;
            float w = (float)(v - z) * s_scale[nl];
            sh[nl][kl] = __float2half_rn(w);
        }
    }
    __syncthreads();

    for (int i = tid; i < 64 * 8; i += 256) {
        int nl = i >> 3;
        int ck = (i & 7) * 8;
        uint4 v = *reinterpret_cast<const uint4*>(&sh[nl][ck]);
        *reinterpret_cast<uint4*>(&g_B[(size_t)(n0 + nl) * KDIM + k0 + ck]) = v;
    }
}

// ========================= Kernel 3: fp16 GEMM (mma.sync) ================
// out[M,N] = A[M,K] * B[N,K]^T + bias
// BM=256 BN=128 BK=32, 256 threads (8 warps as 4m x 2n), warp tile 64x64,
// 4-stage cp.async pipeline, ONE __syncthreads per k-iter.
constexpr int BM = 256, BN = 128, BK = 32;
constexpr int STAGES = 4;
constexpr int LDA = BK + 8;  // 40 halfs = 80B rows (16B-aligned, conflict-free)
constexpr int A_STAGE_ELEMS = BM * LDA;      // 10240 halfs
constexpr int B_STAGE_ELEMS = BN * LDA;      // 5120 halfs
constexpr int GEMM_SMEM = STAGES * (A_STAGE_ELEMS + B_STAGE_ELEMS) * 2;  // 122880 B

__global__ __launch_bounds__(256, 1)
void gemm_f16_kernel(const float* __restrict__ bias, float* __restrict__ out) {
    extern __shared__ __half smem[];
    __half* Abuf = smem;                              // [STAGES][BM][LDA]
    __half* Bbuf = smem + STAGES * A_STAGE_ELEMS;     // [STAGES][BN][LDA]

    const int tid  = threadIdx.x;
    const int lane = tid & 31;
    const int warp = tid >> 5;
    const int m0 = blockIdx.y * BM;
    const int n0 = blockIdx.x * BN;
    const int wm = (warp >> 1) * 64;  // 0/64/128/192
    const int wn = (warp & 1) * 64;   // 0/64

    float acc[4][8][4];
#pragma unroll
    for (int a = 0; a < 4; a++)
#pragma unroll
        for (int b = 0; b < 8; b++)
#pragma unroll
            for (int c = 0; c < 4; c++) acc[a][b][c] = 0.0f;

    constexpr int T = KDIM / BK;  // 128

    // stage loader: A is 256 rows x 4 chunks, B is 128 rows x 4 chunks (16B each)
    auto load_stage = [&](int s, int bk) {
        __half* As = Abuf + s * A_STAGE_ELEMS;
        __half* Bs = Bbuf + s * B_STAGE_ELEMS;
#pragma unroll
        for (int i = 0; i < 4; i++) {
            int id = tid + i * 256;       // 0..1023
            int r = id >> 2, c = id & 3;
            cp_async16(smem_u32(&As[r * LDA + c * 8]),
                       &g_A[(size_t)(m0 + r) * KDIM + bk + c * 8]);
        }
#pragma unroll
        for (int i = 0; i < 2; i++) {
            int id = tid + i * 256;       // 0..511
            int r = id >> 2, c = id & 3;
            cp_async16(smem_u32(&Bs[r * LDA + c * 8]),
                       &g_B[(size_t)(n0 + r) * KDIM + bk + c * 8]);
        }
    };

    // prefetch stages 0..STAGES-2
#pragma unroll
    for (int s = 0; s < STAGES - 1; s++) {
        load_stage(s, s * BK);
        cp_commit();
    }

    for (int t = 0; t < T; t++) {
        cp_wait2();          // stage t resident
        __syncthreads();     // all warps done with slot (t-1)%4 == (t+3)%4

        if (t + STAGES - 1 < T) load_stage((t + STAGES - 1) & 3, (t + STAGES - 1) * BK);
        cp_commit();         // uniform group accounting (empty group ok)

        const int s = t & 3;
        const __half* As = Abuf + s * A_STAGE_ELEMS;
        const __half* Bs = Bbuf + s * B_STAGE_ELEMS;

#pragma unroll
        for (int ks = 0; ks < 2; ks++) {
            uint32_t afr[4][4];
            uint32_t bfr[8][2];
#pragma unroll
            for (int mt = 0; mt < 4; mt++) {
                uint32_t addr = smem_u32(
                    &As[(wm + mt * 16 + (lane & 15)) * LDA + ks * 16 + (lane >> 4) * 8]);
                ldmatrix_x4(afr[mt][0], afr[mt][1], afr[mt][2], afr[mt][3], addr);
            }
#pragma unroll
            for (int nt = 0; nt < 8; nt++) {
                uint32_t addr = smem_u32(
                    &Bs[(wn + nt * 8 + (lane & 7)) * LDA + ks * 16 + ((lane >> 3) & 1) * 8]);
                ldmatrix_x2(bfr[nt][0], bfr[nt][1], addr);
            }
#pragma unroll
            for (int mt = 0; mt < 4; mt++)
#pragma unroll
                for (int nt = 0; nt < 8; nt++)
                    mma_f16(acc[mt][nt][0], acc[mt][nt][1], acc[mt][nt][2], acc[mt][nt][3],
                            afr[mt][0], afr[mt][1], afr[mt][2], afr[mt][3],
                            bfr[nt][0], bfr[nt][1]);
        }
    }

    // --- epilogue: += bias, fp32 stores ---
#pragma unroll
    for (int mt = 0; mt < 4; mt++) {
#pragma unroll
        for (int nt = 0; nt < 8; nt++) {
            int r = m0 + wm + mt * 16 + (lane >> 2);
            int c = n0 + wn + nt * 8 + (lane & 3) * 2;
            float2 bv = *reinterpret_cast<const float2*>(&bias[c]);
            float2 v0 = {acc[mt][nt][0] + bv.x, acc[mt][nt][1] + bv.y};
            float2 v1 = {acc[mt][nt][2] + bv.x, acc[mt][nt][3] + bv.y};
            *reinterpret_cast<float2*>(&out[(size_t)r * NDIM + c])       = v0;
            *reinterpret_cast<float2*>(&out[(size_t)(r + 8) * NDIM + c]) = v1;
        }
    }
}

// ========================= Launch =========================
extern "C" void kernel_launch(void* const* d_in, const int* in_sizes, int n_in,
                              void* d_out, int out_size) {
    const float* x    = (const float*)d_in[0];
    const int*   qw   = (const int*)d_in[1];
    const int*   qz   = (const int*)d_in[2];
    const float* sc   = (const float*)d_in[3];
    const float* bias = (const float*)d_in[4];
    float* out = (float*)d_out;

    // 1) x -> fp16
    {
        size_t total = (size_t)MDIM * KDIM / 8;  // uint4 per thread
        conv_x_kernel<<<(unsigned)(total / 256), 256>>>(x);
    }
    // 2) dequant weights -> fp16 [N][K]
    {
        dim3 grid(NDIM / 64, KDIM / 64);
        dequant_w_kernel<<<grid, 256>>>(qw, qz, sc);
    }
    // 3) fp16 GEMM (mma.sync)
    {
        cudaFuncSetAttribute(gemm_f16_kernel,
                             cudaFuncAttributeMaxDynamicSharedMemorySize, GEMM_SMEM);
        dim3 grid(NDIM / BN, MDIM / BM);
        gemm_f16_kernel<<<grid, 256, GEMM_SMEM>>>(bias, out);
    }
}

// round 4
// speedup vs baseline: 2.8940x; 1.0576x over previous
#include <cuda_runtime.h>
#include <cuda_fp16.h>
#include <cstdint>

// Shapes (fixed for this problem)
constexpr int MDIM = 4096;   // B*S
constexpr int KDIM = 4096;
constexpr int NDIM = 11008;
constexpr int GRP  = 128;

// -----------------------------------------------------------------------
// Scratch (allocation-free rule: __device__ globals)
//   g_A: [M][K] fp16 = fp16(x)
//   g_B: [N][K] fp16 = fp16((v - z) * scale)   (k-contiguous rows)
// -----------------------------------------------------------------------
__device__ __half g_A[(size_t)MDIM * KDIM];
__device__ __half g_B[(size_t)NDIM * KDIM];

// ========================= PTX helpers =========================
__device__ __forceinline__ uint32_t smem_u32(const void* p) {
    return (uint32_t)__cvta_generic_to_shared(p);
}
__device__ __forceinline__ void cp_async16(uint32_t smem, const void* gmem) {
    asm volatile("cp.async.cg.shared.global [%0], [%1], 16;\n"
                 :: "r"(smem), "l"(gmem));
}
__device__ __forceinline__ void cp_commit() {
    asm volatile("cp.async.commit_group;\n");
}
__device__ __forceinline__ void cp_wait2() {
    asm volatile("cp.async.wait_group 2;\n");
}
__device__ __forceinline__ void ldmatrix_x4(uint32_t& r0, uint32_t& r1,
                                            uint32_t& r2, uint32_t& r3,
                                            uint32_t addr) {
    asm volatile("ldmatrix.sync.aligned.m8n8.x4.shared.b16 {%0,%1,%2,%3}, [%4];\n"
                 : "=r"(r0), "=r"(r1), "=r"(r2), "=r"(r3) : "r"(addr));
}
__device__ __forceinline__ void ldmatrix_x2(uint32_t& r0, uint32_t& r1, uint32_t addr) {
    asm volatile("ldmatrix.sync.aligned.m8n8.x2.shared.b16 {%0,%1}, [%2];\n"
                 : "=r"(r0), "=r"(r1) : "r"(addr));
}
__device__ __forceinline__ void mma_f16(float& c0, float& c1, float& c2, float& c3,
                                        uint32_t a0, uint32_t a1, uint32_t a2, uint32_t a3,
                                        uint32_t b0, uint32_t b1) {
    asm volatile("mma.sync.aligned.m16n8k16.row.col.f32.f16.f16.f32 "
                 "{%0,%1,%2,%3}, {%4,%5,%6,%7}, {%8,%9}, {%0,%1,%2,%3};\n"
                 : "+f"(c0), "+f"(c1), "+f"(c2), "+f"(c3)
                 : "r"(a0), "r"(a1), "r"(a2), "r"(a3), "r"(b0), "r"(b1));
}

// ========================= Kernel 1: x -> fp16 =========================
__global__ void conv_x_kernel(const float* __restrict__ x) {
    size_t i = (size_t)blockIdx.x * blockDim.x + threadIdx.x;  // per 8 floats
    const float4* x4 = reinterpret_cast<const float4*>(x);
    float4 a = x4[2 * i];
    float4 b = x4[2 * i + 1];
    __half2 h0 = __floats2half2_rn(a.x, a.y);
    __half2 h1 = __floats2half2_rn(a.z, a.w);
    __half2 h2 = __floats2half2_rn(b.x, b.y);
    __half2 h3 = __floats2half2_rn(b.z, b.w);
    uint4 o;
    o.x = *reinterpret_cast<uint32_t*>(&h0);
    o.y = *reinterpret_cast<uint32_t*>(&h1);
    o.z = *reinterpret_cast<uint32_t*>(&h2);
    o.w = *reinterpret_cast<uint32_t*>(&h3);
    reinterpret_cast<uint4*>(g_A)[i] = o;
}

// ========================= Kernel 2: dequant W -> fp16 [N][K] ===========
__global__ void dequant_w_kernel(const int* __restrict__ qw,
                                 const int* __restrict__ qz,
                                 const float* __restrict__ sc) {
    __shared__ __half sh[64][72];   // [n_local][k_local], row=144B (16B aligned)
    __shared__ float  s_scale[64];
    __shared__ int    s_z[8];

    const int tid = threadIdx.x;
    const int n0 = blockIdx.x * 64;
    const int k0 = blockIdx.y * 64;
    const int group = k0 / GRP;
    const int pw = NDIM / 8;

    if (tid < 64) s_scale[tid] = sc[(size_t)group * NDIM + n0 + tid];
    if (tid < 8)  s_z[tid]     = qz[(size_t)group * pw + n0 / 8 + tid];
    __syncthreads();

    const int shifts[8] = {0, 16, 4, 20, 8, 24, 12, 28};
    for (int i = tid; i < 64 * 8; i += 256) {
        int kl = i >> 3;
        int p  = i & 7;
        int packed = qw[(size_t)(k0 + kl) * pw + n0 / 8 + p];
        int zp = s_z[p];
#pragma unroll
        for (int j = 0; j < 8; j++) {
            int v = (packed >> shifts[j]) & 0xF;
            int z = (zp     >> shifts[j]) & 0xF;
            int nl = p * 8 + j;
            float w = (float)(v - z) * s_scale[nl];
            sh[nl][kl] = __float2half_rn(w);
        }
    }
    __syncthreads();

    for (int i = tid; i < 64 * 8; i += 256) {
        int nl = i >> 3;
        int ck = (i & 7) * 8;
        uint4 v = *reinterpret_cast<const uint4*>(&sh[nl][ck]);
        *reinterpret_cast<uint4*>(&g_B[(size_t)(n0 + nl) * KDIM + k0 + ck]) = v;
    }
}

// ========================= Kernel 3: fp16 GEMM (mma.sync) ================
// out[M,N] = A[M,K] * B[N,K]^T + bias
// BM=128 BN=128 BK=32, 256 threads (8 warps as 2m x 4n), warp tile 64x32,
// 4-stage cp.async pipeline, ONE __syncthreads per k-iter, 2 CTAs/SM.
constexpr int BM = 128, BN = 128, BK = 32;
constexpr int STAGES = 4;
constexpr int LDA = BK + 8;                    // 40 halfs = 80B rows
constexpr int A_STAGE_ELEMS = BM * LDA;        // 5120 halfs
constexpr int B_STAGE_ELEMS = BN * LDA;        // 5120 halfs
constexpr int GEMM_SMEM = STAGES * (A_STAGE_ELEMS + B_STAGE_ELEMS) * 2;  // 81920 B

__global__ __launch_bounds__(256, 2)
void gemm_f16_kernel(const float* __restrict__ bias, float* __restrict__ out) {
    extern __shared__ __half smem[];
    __half* Abuf = smem;                              // [STAGES][BM][LDA]
    __half* Bbuf = smem + STAGES * A_STAGE_ELEMS;     // [STAGES][BN][LDA]

    const int tid  = threadIdx.x;
    const int lane = tid & 31;
    const int warp = tid >> 5;
    const int m0 = blockIdx.y * BM;
    const int n0 = blockIdx.x * BN;
    const int wm = (warp >> 2) * 64;  // 0/64
    const int wn = (warp & 3) * 32;   // 0/32/64/96

    float acc[4][4][4];
#pragma unroll
    for (int a = 0; a < 4; a++)
#pragma unroll
        for (int b = 0; b < 4; b++)
#pragma unroll
            for (int c = 0; c < 4; c++) acc[a][b][c] = 0.0f;

    constexpr int T = KDIM / BK;  // 128

    // stage loader: A/B each 128 rows x 4 chunks of 16B -> 1024 cp / 256 thr
    auto load_stage = [&](int s, int bk) {
        __half* As = Abuf + s * A_STAGE_ELEMS;
        __half* Bs = Bbuf + s * B_STAGE_ELEMS;
#pragma unroll
        for (int i = 0; i < 2; i++) {
            int id = tid + i * 256;       // 0..511
            int r = id >> 2, c = id & 3;
            cp_async16(smem_u32(&As[r * LDA + c * 8]),
                       &g_A[(size_t)(m0 + r) * KDIM + bk + c * 8]);
            cp_async16(smem_u32(&Bs[r * LDA + c * 8]),
                       &g_B[(size_t)(n0 + r) * KDIM + bk + c * 8]);
        }
    };

    // prefetch stages 0..2
#pragma unroll
    for (int s = 0; s < STAGES - 1; s++) {
        load_stage(s, s * BK);
        cp_commit();
    }

    for (int t = 0; t < T; t++) {
        cp_wait2();          // stage t resident
        __syncthreads();     // all warps done with slot being overwritten next

        if (t + STAGES - 1 < T) load_stage((t + STAGES - 1) & 3, (t + STAGES - 1) * BK);
        cp_commit();         // uniform group accounting (empty group ok)

        const int s = t & 3;
        const __half* As = Abuf + s * A_STAGE_ELEMS;
        const __half* Bs = Bbuf + s * B_STAGE_ELEMS;

#pragma unroll
        for (int ks = 0; ks < 2; ks++) {
            uint32_t afr[4][4];
            uint32_t bfr[4][2];
#pragma unroll
            for (int mt = 0; mt < 4; mt++) {
                uint32_t addr = smem_u32(
                    &As[(wm + mt * 16 + (lane & 15)) * LDA + ks * 16 + (lane >> 4) * 8]);
                ldmatrix_x4(afr[mt][0], afr[mt][1], afr[mt][2], afr[mt][3], addr);
            }
#pragma unroll
            for (int nt = 0; nt < 4; nt++) {
                uint32_t addr = smem_u32(
                    &Bs[(wn + nt * 8 + (lane & 7)) * LDA + ks * 16 + ((lane >> 3) & 1) * 8]);
                ldmatrix_x2(bfr[nt][0], bfr[nt][1], addr);
            }
#pragma unroll
            for (int mt = 0; mt < 4; mt++)
#pragma unroll
                for (int nt = 0; nt < 4; nt++)
                    mma_f16(acc[mt][nt][0], acc[mt][nt][1], acc[mt][nt][2], acc[mt][nt][3],
                            afr[mt][0], afr[mt][1], afr[mt][2], afr[mt][3],
                            bfr[nt][0], bfr[nt][1]);
        }
    }

    // --- epilogue: += bias, fp32 stores ---
#pragma unroll
    for (int mt = 0; mt < 4; mt++) {
#pragma unroll
        for (int nt = 0; nt < 4; nt++) {
            int r = m0 + wm + mt * 16 + (lane >> 2);
            int c = n0 + wn + nt * 8 + (lane & 3) * 2;
            float2 bv = *reinterpret_cast<const float2*>(&bias[c]);
            float2 v0 = {acc[mt][nt][0] + bv.x, acc[mt][nt][1] + bv.y};
            float2 v1 = {acc[mt][nt][2] + bv.x, acc[mt][nt][3] + bv.y};
            *reinterpret_cast<float2*>(&out[(size_t)r * NDIM + c])       = v0;
            *reinterpret_cast<float2*>(&out[(size_t)(r + 8) * NDIM + c]) = v1;
        }
    }
}

// ========================= Launch =========================
extern "C" void kernel_launch(void* const* d_in, const int* in_sizes, int n_in,
                              void* d_out, int out_size) {
    const float* x    = (const float*)d_in[0];
    const int*   qw   = (const int*)d_in[1];
    const int*   qz   = (const int*)d_in[2];
    const float* sc   = (const float*)d_in[3];
    const float* bias = (const float*)d_in[4];
    float* out = (float*)d_out;

    // 1) x -> fp16
    {
        size_t total = (size_t)MDIM * KDIM / 8;  // uint4 per thread
        conv_x_kernel<<<(unsigned)(total / 256), 256>>>(x);
    }
    // 2) dequant weights -> fp16 [N][K]
    {
        dim3 grid(NDIM / 64, KDIM / 64);
        dequant_w_kernel<<<grid, 256>>>(qw, qz, sc);
    }
    // 3) fp16 GEMM (mma.sync)
    {
        cudaFuncSetAttribute(gemm_f16_kernel,
                             cudaFuncAttributeMaxDynamicSharedMemorySize, GEMM_SMEM);
        dim3 grid(NDIM / BN, MDIM / BM);
        gemm_f16_kernel<<<grid, 256, GEMM_SMEM>>>(bias, out);
    }
}

// round 6
// speedup vs baseline: 3.5277x; 1.2190x over previous
#include <cuda_runtime.h>
#include <cuda_fp16.h>
#include <cstdint>

// Shapes (fixed for this problem)
constexpr int MDIM = 4096;   // B*S
constexpr int KDIM = 4096;
constexpr int NDIM = 11008;
constexpr int GRP  = 128;

// -----------------------------------------------------------------------
// Scratch (allocation-free rule: __device__ globals)
//   g_A: [M][K] fp16 = fp16(x)
//   g_B: [N][K] fp16 = fp16((v - z) * scale)   (k-contiguous rows)
// -----------------------------------------------------------------------
__device__ __half g_A[(size_t)MDIM * KDIM];
__device__ __half g_B[(size_t)NDIM * KDIM];

// ========================= PTX helpers =========================
__device__ __forceinline__ uint32_t smem_u32(const void* p) {
    return (uint32_t)__cvta_generic_to_shared(p);
}
__device__ __forceinline__ void cp_async16(uint32_t smem, const void* gmem) {
    asm volatile("cp.async.cg.shared.global [%0], [%1], 16;\n"
                 :: "r"(smem), "l"(gmem));
}
__device__ __forceinline__ void cp_commit() {
    asm volatile("cp.async.commit_group;\n");
}
__device__ __forceinline__ void cp_wait1() {
    asm volatile("cp.async.wait_group 1;\n");
}
__device__ __forceinline__ void ldmatrix_x4(uint32_t& r0, uint32_t& r1,
                                            uint32_t& r2, uint32_t& r3,
                                            uint32_t addr) {
    asm volatile("ldmatrix.sync.aligned.m8n8.x4.shared.b16 {%0,%1,%2,%3}, [%4];\n"
                 : "=r"(r0), "=r"(r1), "=r"(r2), "=r"(r3) : "r"(addr));
}
__device__ __forceinline__ void mma_f16(float& c0, float& c1, float& c2, float& c3,
                                        uint32_t a0, uint32_t a1, uint32_t a2, uint32_t a3,
                                        uint32_t b0, uint32_t b1) {
    asm volatile("mma.sync.aligned.m16n8k16.row.col.f32.f16.f16.f32 "
                 "{%0,%1,%2,%3}, {%4,%5,%6,%7}, {%8,%9}, {%0,%1,%2,%3};\n"
                 : "+f"(c0), "+f"(c1), "+f"(c2), "+f"(c3)
                 : "r"(a0), "r"(a1), "r"(a2), "r"(a3), "r"(b0), "r"(b1));
}

// ========================= Kernel 1: merged prep ========================
// Blocks [0, CONV_BLOCKS)          : x (fp32) -> g_A (fp16)
// Blocks [CONV_BLOCKS, +DQ_BLOCKS) : dequant W tile (128 k x 64 n) -> g_B
constexpr int CONV_BLOCKS = (MDIM * KDIM / 8) / 256;         // 8192
constexpr int DQ_NT = NDIM / 64;                              // 172
constexpr int DQ_KT = KDIM / 128;                             // 32
constexpr int DQ_BLOCKS = DQ_NT * DQ_KT;                      // 5504

__global__ void prep_kernel(const float* __restrict__ x,
                            const int* __restrict__ qw,
                            const int* __restrict__ qz,
                            const float* __restrict__ sc) {
    const int tid = threadIdx.x;

    if (blockIdx.x < CONV_BLOCKS) {
        // ---- conv x -> fp16, 8 floats per thread ----
        size_t i = (size_t)blockIdx.x * 256 + tid;
        const float4* x4 = reinterpret_cast<const float4*>(x);
        float4 a = x4[2 * i];
        float4 b = x4[2 * i + 1];
        __half2 h0 = __floats2half2_rn(a.x, a.y);
        __half2 h1 = __floats2half2_rn(a.z, a.w);
        __half2 h2 = __floats2half2_rn(b.x, b.y);
        __half2 h3 = __floats2half2_rn(b.z, b.w);
        uint4 o;
        o.x = *reinterpret_cast<uint32_t*>(&h0);
        o.y = *reinterpret_cast<uint32_t*>(&h1);
        o.z = *reinterpret_cast<uint32_t*>(&h2);
        o.w = *reinterpret_cast<uint32_t*>(&h3);
        reinterpret_cast<uint4*>(g_A)[i] = o;
        return;
    }

    // ---- dequant W: tile 128 k x 64 n (one quant group) ----
    __shared__ __half sh[64][136];   // [n_local][k_local(128)+8 pad] rows 272B
    __shared__ float  s_scale[64];
    __shared__ int    s_z[8];

    const int t  = blockIdx.x - CONV_BLOCKS;
    const int n0 = (t % DQ_NT) * 64;
    const int k0 = (t / DQ_NT) * 128;
    const int group = k0 / GRP;        // k-tile == one group exactly
    const int pw = NDIM / 8;

    if (tid < 64) s_scale[tid] = sc[(size_t)group * NDIM + n0 + tid];
    if (tid < 8)  s_z[tid]     = qz[(size_t)group * pw + n0 / 8 + tid];
    __syncthreads();

    const int shifts[8] = {0, 16, 4, 20, 8, 24, 12, 28};
#pragma unroll
    for (int it = 0; it < 4; it++) {
        int i = tid + it * 256;        // 0..1023
        int kl = i >> 3;               // 0..127
        int p  = i & 7;
        int packed = qw[(size_t)(k0 + kl) * pw + n0 / 8 + p];
        int zp = s_z[p];
#pragma unroll
        for (int j = 0; j < 8; j++) {
            int v = (packed >> shifts[j]) & 0xF;
            int z = (zp     >> shifts[j]) & 0xF;
            int nl = p * 8 + j;
            sh[nl][kl] = __float2half_rn((float)(v - z) * s_scale[nl]);
        }
    }
    __syncthreads();

#pragma unroll
    for (int it = 0; it < 4; it++) {
        int i = tid + it * 256;        // 0..1023
        int nl = i >> 4;               // 0..63
        int ck = (i & 15) * 8;         // 0..120
        uint4 v = *reinterpret_cast<const uint4*>(&sh[nl][ck]);
        *reinterpret_cast<uint4*>(&g_B[(size_t)(n0 + nl) * KDIM + k0 + ck]) = v;
    }
}

// ========================= Kernel 2: fp16 GEMM (mma.sync) ================
// out[M,N] = A[M,K] * B[N,K]^T + bias
// BM=128 BN=128 BK=64, 256 threads (8 warps as 2m x 4n), warp tile 64x32,
// 3-stage cp.async pipeline, ONE __syncthreads per 64-k, 2 CTAs/SM.
constexpr int BM = 128, BN = 128, BK = 64;
constexpr int STAGES = 3;
constexpr int LDA = BK + 8;                   // 72 halfs = 144B rows
constexpr int STAGE_ELEMS = BM * LDA;         // 9216 halfs (A or B)
constexpr int GEMM_SMEM = STAGES * STAGE_ELEMS * 2 * 2;   // 110592 B

__global__ __launch_bounds__(256, 2)
void gemm_f16_kernel(const float* __restrict__ bias, float* __restrict__ out) {
    extern __shared__ __half smem[];
    __half* Abuf = smem;                            // [3][128][72]
    __half* Bbuf = smem + STAGES * STAGE_ELEMS;     // [3][128][72]

    const int tid  = threadIdx.x;
    const int lane = tid & 31;
    const int warp = tid >> 5;
    const int m0 = blockIdx.y * BM;
    const int n0 = blockIdx.x * BN;
    const int wm = (warp >> 2) * 64;  // 0/64
    const int wn = (warp & 3) * 32;   // 0/32/64/96

    float acc[4][4][4];
#pragma unroll
    for (int a = 0; a < 4; a++)
#pragma unroll
        for (int b = 0; b < 4; b++)
#pragma unroll
            for (int c = 0; c < 4; c++) acc[a][b][c] = 0.0f;

    constexpr int T = KDIM / BK;  // 64

    // stage loader: A/B each 128 rows x 8 chunks of 16B -> 2048 cp / 256 thr
    auto load_stage = [&](int s, int bk) {
        __half* As = Abuf + s * STAGE_ELEMS;
        __half* Bs = Bbuf + s * STAGE_ELEMS;
#pragma unroll
        for (int i = 0; i < 4; i++) {
            int id = tid + i * 256;       // 0..1023
            int r = id >> 3, c = id & 7;
            cp_async16(smem_u32(&As[r * LDA + c * 8]),
                       &g_A[(size_t)(m0 + r) * KDIM + bk + c * 8]);
            cp_async16(smem_u32(&Bs[r * LDA + c * 8]),
                       &g_B[(size_t)(n0 + r) * KDIM + bk + c * 8]);
        }
    };

    load_stage(0, 0);  cp_commit();
    load_stage(1, BK); cp_commit();

    int s = 0;
    for (int t = 0; t < T; t++) {
        cp_wait1();          // stage t resident
        __syncthreads();     // overwritten slot provably consumed

        if (t + 2 < T) {
            int ns = s + 2;
            if (ns >= STAGES) ns -= STAGES;   // FIXED: proper modular index
            load_stage(ns, (t + 2) * BK);
        }
        cp_commit();         // uniform accounting (empty group at tail ok)

        const __half* As = Abuf + s * STAGE_ELEMS;
        const __half* Bs = Bbuf + s * STAGE_ELEMS;

#pragma unroll
        for (int ks = 0; ks < 4; ks++) {
            uint32_t afr[4][4];
            uint32_t bfr[4][2];
#pragma unroll
            for (int mt = 0; mt < 4; mt++) {
                uint32_t addr = smem_u32(
                    &As[(wm + mt * 16 + (lane & 15)) * LDA + ks * 16 + (lane >> 4) * 8]);
                ldmatrix_x4(afr[mt][0], afr[mt][1], afr[mt][2], afr[mt][3], addr);
            }
            // B: two x4 loads cover 4 n8-subtiles (verified lane mapping)
#pragma unroll
            for (int nt2 = 0; nt2 < 2; nt2++) {
                int row = wn + nt2 * 16 + ((lane >> 4) << 3) + (lane & 7);
                int col = ks * 16 + (((lane >> 3) & 1) << 3);
                uint32_t addr = smem_u32(&Bs[row * LDA + col]);
                ldmatrix_x4(bfr[nt2 * 2][0], bfr[nt2 * 2][1],
                            bfr[nt2 * 2 + 1][0], bfr[nt2 * 2 + 1][1], addr);
            }
#pragma unroll
            for (int mt = 0; mt < 4; mt++)
#pragma unroll
                for (int nt = 0; nt < 4; nt++)
                    mma_f16(acc[mt][nt][0], acc[mt][nt][1], acc[mt][nt][2], acc[mt][nt][3],
                            afr[mt][0], afr[mt][1], afr[mt][2], afr[mt][3],
                            bfr[nt][0], bfr[nt][1]);
        }
        if (++s == STAGES) s = 0;
    }

    // --- epilogue: += bias, fp32 stores ---
#pragma unroll
    for (int mt = 0; mt < 4; mt++) {
#pragma unroll
        for (int nt = 0; nt < 4; nt++) {
            int r = m0 + wm + mt * 16 + (lane >> 2);
            int c = n0 + wn + nt * 8 + (lane & 3) * 2;
            float2 bv = *reinterpret_cast<const float2*>(&bias[c]);
            float2 v0 = {acc[mt][nt][0] + bv.x, acc[mt][nt][1] + bv.y};
            float2 v1 = {acc[mt][nt][2] + bv.x, acc[mt][nt][3] + bv.y};
            *reinterpret_cast<float2*>(&out[(size_t)r * NDIM + c])       = v0;
            *reinterpret_cast<float2*>(&out[(size_t)(r + 8) * NDIM + c]) = v1;
        }
    }
}

// ========================= Launch =========================
extern "C" void kernel_launch(void* const* d_in, const int* in_sizes, int n_in,
                              void* d_out, int out_size) {
    const float* x    = (const float*)d_in[0];
    const int*   qw   = (const int*)d_in[1];
    const int*   qz   = (const int*)d_in[2];
    const float* sc   = (const float*)d_in[3];
    const float* bias = (const float*)d_in[4];
    float* out = (float*)d_out;

    // 1) merged prep: x->fp16  ||  dequant W->fp16
    prep_kernel<<<CONV_BLOCKS + DQ_BLOCKS, 256>>>(x, qw, qz, sc);

    // 2) fp16 GEMM (mma.sync)
    cudaFuncSetAttribute(gemm_f16_kernel,
                         cudaFuncAttributeMaxDynamicSharedMemorySize, GEMM_SMEM);
    dim3 grid(NDIM / BN, MDIM / BM);
    gemm_f16_kernel<<<grid, 256, GEMM_SMEM>>>(bias, out);
}

// round 8
// speedup vs baseline: 4.1022x; 1.1628x over previous
#include <cuda_runtime.h>
#include <cuda_fp16.h>
#include <cstdint>

// Shapes (fixed for this problem)
constexpr int MDIM = 4096;   // B*S
constexpr int KDIM = 4096;
constexpr int NDIM = 11008;
constexpr int GRP  = 128;

// -----------------------------------------------------------------------
// Scratch (allocation-free rule: __device__ globals)
//   g_A: [M][K] fp16 = fp16(x)
//   g_B: [N][K] fp16 = fp16((v - z) * scale)   (k-contiguous rows)
// -----------------------------------------------------------------------
__device__ __half g_A[(size_t)MDIM * KDIM];
__device__ __half g_B[(size_t)NDIM * KDIM];

// ========================= PTX helpers =========================
__device__ __forceinline__ uint32_t smem_u32(const void* p) {
    return (uint32_t)__cvta_generic_to_shared(p);
}
__device__ __forceinline__ void cp_async16(uint32_t smem, const void* gmem) {
    asm volatile("cp.async.cg.shared.global [%0], [%1], 16;\n"
                 :: "r"(smem), "l"(gmem));
}
__device__ __forceinline__ void cp_commit() {
    asm volatile("cp.async.commit_group;\n");
}
__device__ __forceinline__ void cp_wait1() {
    asm volatile("cp.async.wait_group 1;\n");
}
__device__ __forceinline__ void ldmatrix_x4(uint32_t& r0, uint32_t& r1,
                                            uint32_t& r2, uint32_t& r3,
                                            uint32_t addr) {
    asm volatile("ldmatrix.sync.aligned.m8n8.x4.shared.b16 {%0,%1,%2,%3}, [%4];\n"
                 : "=r"(r0), "=r"(r1), "=r"(r2), "=r"(r3) : "r"(addr));
}
__device__ __forceinline__ void mma_f16(float& c0, float& c1, float& c2, float& c3,
                                        uint32_t a0, uint32_t a1, uint32_t a2, uint32_t a3,
                                        uint32_t b0, uint32_t b1) {
    asm volatile("mma.sync.aligned.m16n8k16.row.col.f32.f16.f16.f32 "
                 "{%0,%1,%2,%3}, {%4,%5,%6,%7}, {%8,%9}, {%0,%1,%2,%3};\n"
                 : "+f"(c0), "+f"(c1), "+f"(c2), "+f"(c3)
                 : "r"(a0), "r"(a1), "r"(a2), "r"(a3), "r"(b0), "r"(b1));
}
// SW128-style swizzle on 128B rows: XOR bits [6:4] with bits [9:7]
__device__ __forceinline__ uint32_t swz(uint32_t o) {
    return o ^ ((o >> 3) & 0x70);
}

// ========================= Kernel 1: merged prep ========================
constexpr int CONV_BLOCKS = (MDIM * KDIM / 8) / 256;         // 8192
constexpr int DQ_NT = NDIM / 64;                              // 172
constexpr int DQ_KT = KDIM / 128;                             // 32
constexpr int DQ_BLOCKS = DQ_NT * DQ_KT;                      // 5504

__global__ void prep_kernel(const float* __restrict__ x,
                            const int* __restrict__ qw,
                            const int* __restrict__ qz,
                            const float* __restrict__ sc) {
    const int tid = threadIdx.x;

    if (blockIdx.x < CONV_BLOCKS) {
        size_t i = (size_t)blockIdx.x * 256 + tid;
        const float4* x4 = reinterpret_cast<const float4*>(x);
        float4 a = x4[2 * i];
        float4 b = x4[2 * i + 1];
        __half2 h0 = __floats2half2_rn(a.x, a.y);
        __half2 h1 = __floats2half2_rn(a.z, a.w);
        __half2 h2 = __floats2half2_rn(b.x, b.y);
        __half2 h3 = __floats2half2_rn(b.z, b.w);
        uint4 o;
        o.x = *reinterpret_cast<uint32_t*>(&h0);
        o.y = *reinterpret_cast<uint32_t*>(&h1);
        o.z = *reinterpret_cast<uint32_t*>(&h2);
        o.w = *reinterpret_cast<uint32_t*>(&h3);
        reinterpret_cast<uint4*>(g_A)[i] = o;
        return;
    }

    // ---- dequant W: tile 128 k x 64 n (one quant group) ----
    __shared__ __half sh[64][136];
    __shared__ float  s_scale[64];
    __shared__ int    s_z[8];

    const int t  = blockIdx.x - CONV_BLOCKS;
    const int n0 = (t % DQ_NT) * 64;
    const int k0 = (t / DQ_NT) * 128;
    const int group = k0 / GRP;
    const int pw = NDIM / 8;

    if (tid < 64) s_scale[tid] = sc[(size_t)group * NDIM + n0 + tid];
    if (tid < 8)  s_z[tid]     = qz[(size_t)group * pw + n0 / 8 + tid];
    __syncthreads();

    const int shifts[8] = {0, 16, 4, 20, 8, 24, 12, 28};
#pragma unroll
    for (int it = 0; it < 4; it++) {
        int i = tid + it * 256;
        int kl = i >> 3;
        int p  = i & 7;
        int packed = qw[(size_t)(k0 + kl) * pw + n0 / 8 + p];
        int zp = s_z[p];
#pragma unroll
        for (int j = 0; j < 8; j++) {
            int v = (packed >> shifts[j]) & 0xF;
            int z = (zp     >> shifts[j]) & 0xF;
            int nl = p * 8 + j;
            sh[nl][kl] = __float2half_rn((float)(v - z) * s_scale[nl]);
        }
    }
    __syncthreads();

#pragma unroll
    for (int it = 0; it < 4; it++) {
        int i = tid + it * 256;
        int nl = i >> 4;
        int ck = (i & 15) * 8;
        uint4 v = *reinterpret_cast<const uint4*>(&sh[nl][ck]);
        *reinterpret_cast<uint4*>(&g_B[(size_t)(n0 + nl) * KDIM + k0 + ck]) = v;
    }
}

// ========================= Kernel 2: fp16 GEMM (mma.sync) ================
// out[M,N] = A[M,K] * B[N,K]^T + bias
// BM=128 BN=64 BK=64, 256 threads (8 warps as 4m x 2n), warp tile 32x32,
// swizzled smem (no pad), 3-stage cp.async, 3 CTAs/SM (24 warps).
constexpr int BM = 128, BN = 64, BK = 64;
constexpr int STAGES = 3;
constexpr int A_STAGE_BYTES = BM * BK * 2;     // 16384
constexpr int B_STAGE_BYTES = BN * BK * 2;     // 8192
constexpr int STAGE_BYTES = A_STAGE_BYTES + B_STAGE_BYTES;   // 24576
constexpr int GEMM_SMEM = STAGES * STAGE_BYTES;              // 73728

__global__ __launch_bounds__(256, 3)
void gemm_f16_kernel(const float* __restrict__ bias, float* __restrict__ out) {
    extern __shared__ __align__(128) uint8_t smem[];
    const uint32_t sbase = smem_u32(smem);

    const int tid  = threadIdx.x;
    const int lane = tid & 31;
    const int warp = tid >> 5;
    const int m0 = blockIdx.x * BM;       // m-major in x: wave covers all m
    const int n0 = blockIdx.y * BN;
    const int wm = (warp & 3) * 32;       // 0/32/64/96
    const int wn = (warp >> 2) * 32;      // 0/32

    float acc[2][4][4];
#pragma unroll
    for (int a = 0; a < 2; a++)
#pragma unroll
        for (int b = 0; b < 4; b++)
#pragma unroll
            for (int c = 0; c < 4; c++) acc[a][b][c] = 0.0f;

    constexpr int T = KDIM / BK;  // 64

    // RAW (unswizzled) per-lane byte offsets; swizzle applied AFTER adding
    // ks*32 (col stays < 128, so the add never carries into the XOR source).
    uint32_t araw[2], braw[2];
#pragma unroll
    for (int mt = 0; mt < 2; mt++)
        araw[mt] = (uint32_t)(wm + mt * 16 + (lane & 15)) * 128 +
                   ((uint32_t)(lane >> 4) << 4);
#pragma unroll
    for (int nt2 = 0; nt2 < 2; nt2++)
        braw[nt2] = (uint32_t)(wn + nt2 * 16 + ((lane >> 4) << 3) + (lane & 7)) * 128 +
                    (((uint32_t)(lane >> 3) & 1) << 4);

    // stage loader: A 128 rows x 8 chunks, B 64 rows x 8 chunks (16B each)
    auto load_stage = [&](int s, int bk) {
        uint32_t Ab = sbase + s * STAGE_BYTES;
        uint32_t Bb = Ab + A_STAGE_BYTES;
#pragma unroll
        for (int i = 0; i < 4; i++) {
            int id = tid + i * 256;       // 0..1023
            int r = id >> 3, c = id & 7;
            cp_async16(Ab + swz((uint32_t)r * 128 + (uint32_t)c * 16),
                       &g_A[(size_t)(m0 + r) * KDIM + bk + c * 8]);
        }
#pragma unroll
        for (int i = 0; i < 2; i++) {
            int id = tid + i * 256;       // 0..511
            int r = id >> 3, c = id & 7;
            cp_async16(Bb + swz((uint32_t)r * 128 + (uint32_t)c * 16),
                       &g_B[(size_t)(n0 + r) * KDIM + bk + c * 8]);
        }
    };

    load_stage(0, 0);  cp_commit();
    load_stage(1, BK); cp_commit();

    int s = 0;
    for (int t = 0; t < T; t++) {
        cp_wait1();          // stage t resident
        __syncthreads();     // overwritten slot provably consumed

        if (t + 2 < T) {
            int ns = s + 2;
            if (ns >= STAGES) ns -= STAGES;
            load_stage(ns, (t + 2) * BK);
        }
        cp_commit();

        const uint32_t stageA = sbase + s * STAGE_BYTES;
        const uint32_t stageB = stageA + A_STAGE_BYTES;

#pragma unroll
        for (int ks = 0; ks < 4; ks++) {
            uint32_t afr[2][4];
            uint32_t bfr[4][2];
#pragma unroll
            for (int mt = 0; mt < 2; mt++)
                ldmatrix_x4(afr[mt][0], afr[mt][1], afr[mt][2], afr[mt][3],
                            stageA + swz(araw[mt] + ks * 32));   // FIXED: swz after add
#pragma unroll
            for (int nt2 = 0; nt2 < 2; nt2++)
                ldmatrix_x4(bfr[nt2 * 2][0], bfr[nt2 * 2][1],
                            bfr[nt2 * 2 + 1][0], bfr[nt2 * 2 + 1][1],
                            stageB + swz(braw[nt2] + ks * 32));  // FIXED: swz after add
#pragma unroll
            for (int mt = 0; mt < 2; mt++)
#pragma unroll
                for (int nt = 0; nt < 4; nt++)
                    mma_f16(acc[mt][nt][0], acc[mt][nt][1], acc[mt][nt][2], acc[mt][nt][3],
                            afr[mt][0], afr[mt][1], afr[mt][2], afr[mt][3],
                            bfr[nt][0], bfr[nt][1]);
        }
        if (++s == STAGES) s = 0;
    }

    // --- epilogue: += bias, fp32 stores ---
#pragma unroll
    for (int mt = 0; mt < 2; mt++) {
#pragma unroll
        for (int nt = 0; nt < 4; nt++) {
            int r = m0 + wm + mt * 16 + (lane >> 2);
            int c = n0 + wn + nt * 8 + (lane & 3) * 2;
            float2 bv = *reinterpret_cast<const float2*>(&bias[c]);
            float2 v0 = {acc[mt][nt][0] + bv.x, acc[mt][nt][1] + bv.y};
            float2 v1 = {acc[mt][nt][2] + bv.x, acc[mt][nt][3] + bv.y};
            *reinterpret_cast<float2*>(&out[(size_t)r * NDIM + c])       = v0;
            *reinterpret_cast<float2*>(&out[(size_t)(r + 8) * NDIM + c]) = v1;
        }
    }
}

// ========================= Launch =========================
extern "C" void kernel_launch(void* const* d_in, const int* in_sizes, int n_in,
                              void* d_out, int out_size) {
    const float* x    = (const float*)d_in[0];
    const int*   qw   = (const int*)d_in[1];
    const int*   qz   = (const int*)d_in[2];
    const float* sc   = (const float*)d_in[3];
    const float* bias = (const float*)d_in[4];
    float* out = (float*)d_out;

    // 1) merged prep: x->fp16  ||  dequant W->fp16
    prep_kernel<<<CONV_BLOCKS + DQ_BLOCKS, 256>>>(x, qw, qz, sc);

    // 2) fp16 GEMM (mma.sync), 3 CTAs/SM
    cudaFuncSetAttribute(gemm_f16_kernel,
                         cudaFuncAttributeMaxDynamicSharedMemorySize, GEMM_SMEM);
    dim3 grid(MDIM / BM, NDIM / BN);   // m-major for L2 reuse of A within wave
    gemm_f16_kernel<<<grid, 256, GEMM_SMEM>>>(bias, out);
}